// round 1
// baseline (speedup 1.0000x reference)
#include <cuda_runtime.h>
#include <math.h>

// Problem constants
#define Bb 4
#define Tt 2048
#define Dd 1024
#define MT (Bb*Tt)          // 8192
#define ETA 0.1f

// GEMM tiling
#define BM 128
#define BN 128
#define BK 16
#define TM 8
#define TN 8

// ---------------- scratch (static device globals; no allocation allowed) ----------------
__device__ float g_G[2][(long)Dd*Dd];        // symmetrized, zero-diag G for q and k
__device__ float g_qu[(long)MT*Dd];          // u_q
__device__ float g_ku[(long)MT*Dd];          // u_k
__device__ float g_vv[(long)MT*Dd];          // value projection
__device__ float g_vst[(long)MT*Dd];         // LCA membrane state v (reused q then k)
__device__ float g_aq[2][(long)MT*Dd];       // ping-pong sparse code for q
__device__ float g_ak[2][(long)MT*Dd];       // ping-pong sparse code for k
__device__ float g_scores[(long)Bb*Tt*Tt];   // attention scores / probs (in-place softmax)
__device__ float g_ao[(long)MT*Dd];          // attn @ v

// ---------------- GEMM ----------------
// C[M,N] = A[M,K] @ op(B), op(B)=B^T if TRANSB (B is [N,K]) else B ([K,N]).
// causal==1 : skip blocks strictly above the diagonal (scores GEMM; M==N).
// causal==2 : limit K loop to min(K, m0+BM) (attn@v GEMM: attn rows are 0 past diag).
// LCA epilogue: treat acc as t = a@G, then v' = v + ETA*(u - v - t) (in-place),
//               a_out = soft_threshold(v', lam), lam = exp(*loglam).
template<bool TRANSB, bool LCA>
__global__ __launch_bounds__(256) void gemm_k(
    const float* __restrict__ A, const float* __restrict__ B,
    float* __restrict__ C, int M, int N, int K,
    long sA, long sB, long sC, int causal,
    const float* __restrict__ U, float* __restrict__ V,
    float* __restrict__ Ao, const float* __restrict__ loglam)
{
    const int m0 = blockIdx.y * BM;
    const int n0 = blockIdx.x * BN;
    if (!LCA && causal == 1 && n0 > m0) return;   // fully-masked score block
    const int zb = blockIdx.z;
    A += (long)zb * sA;
    B += (long)zb * sB;
    const int Kend = (!LCA && causal == 2) ? min(K, m0 + BM) : K;

    __shared__ float As[BK][BM];
    __shared__ float Bs[BK][BN];

    const int tid = threadIdx.x;
    const int tr = tid >> 4;            // 0..15
    const int tc = tid & 15;            // 0..15

    float acc[TM][TN];
    #pragma unroll
    for (int i = 0; i < TM; i++)
        #pragma unroll
        for (int j = 0; j < TN; j++) acc[i][j] = 0.f;

    const int lr = tid >> 2;            // 0..63
    const int lc = (tid & 3) << 2;      // 0,4,8,12

    for (int k0 = 0; k0 < Kend; k0 += BK) {
        // ---- load A tile (transposed store As[k][m]) ----
        {
            float4 a0 = *(const float4*)(A + (long)(m0 + lr     ) * K + k0 + lc);
            float4 a1 = *(const float4*)(A + (long)(m0 + lr + 64) * K + k0 + lc);
            As[lc+0][lr]    = a0.x; As[lc+1][lr]    = a0.y; As[lc+2][lr]    = a0.z; As[lc+3][lr]    = a0.w;
            As[lc+0][lr+64] = a1.x; As[lc+1][lr+64] = a1.y; As[lc+2][lr+64] = a1.z; As[lc+3][lr+64] = a1.w;
        }
        // ---- load B tile into Bs[k][n] ----
        if (TRANSB) {
            float4 b0 = *(const float4*)(B + (long)(n0 + lr     ) * K + k0 + lc);
            float4 b1 = *(const float4*)(B + (long)(n0 + lr + 64) * K + k0 + lc);
            Bs[lc+0][lr]    = b0.x; Bs[lc+1][lr]    = b0.y; Bs[lc+2][lr]    = b0.z; Bs[lc+3][lr]    = b0.w;
            Bs[lc+0][lr+64] = b1.x; Bs[lc+1][lr+64] = b1.y; Bs[lc+2][lr+64] = b1.z; Bs[lc+3][lr+64] = b1.w;
        } else {
            const int rr = tid >> 5;          // 0..7
            const int cc = (tid & 31) << 2;   // 0..124
            *(float4*)&Bs[rr    ][cc] = *(const float4*)(B + (long)(k0 + rr    ) * N + n0 + cc);
            *(float4*)&Bs[rr + 8][cc] = *(const float4*)(B + (long)(k0 + rr + 8) * N + n0 + cc);
        }
        __syncthreads();

        #pragma unroll
        for (int kk = 0; kk < BK; kk++) {
            float af[TM], bf[TN];
            #pragma unroll
            for (int i = 0; i < TM; i++) af[i] = As[kk][tr*TM + i];
            #pragma unroll
            for (int j = 0; j < TN; j++) bf[j] = Bs[kk][tc*TN + j];
            #pragma unroll
            for (int i = 0; i < TM; i++)
                #pragma unroll
                for (int j = 0; j < TN; j++)
                    acc[i][j] = fmaf(af[i], bf[j], acc[i][j]);
        }
        __syncthreads();
    }

    if (!LCA) {
        C += (long)zb * sC;
        #pragma unroll
        for (int i = 0; i < TM; i++) {
            long off = (long)(m0 + tr*TM + i) * N + n0 + tc*TN;
            *(float4*)(C + off)     = make_float4(acc[i][0], acc[i][1], acc[i][2], acc[i][3]);
            *(float4*)(C + off + 4) = make_float4(acc[i][4], acc[i][5], acc[i][6], acc[i][7]);
        }
    } else {
        const float lam = expf(loglam[0]);
        #pragma unroll
        for (int i = 0; i < TM; i++) {
            long off = (long)(m0 + tr*TM + i) * N + n0 + tc*TN;
            #pragma unroll
            for (int j = 0; j < TN; j++) {
                float t  = acc[i][j];
                float u  = U[off + j];
                float v  = V[off + j];
                float vn = v + ETA * (u - v - t);
                V[off + j] = vn;
                float mag = fabsf(vn) - lam;
                Ao[off + j] = (mag > 0.f) ? copysignf(mag, vn) : 0.f;
            }
        }
    }
}

// ---------------- elementwise kernels ----------------
__global__ __launch_bounds__(256) void prep_G_k(const float* __restrict__ Graw,
                                                float* __restrict__ G)
{
    long idx = (long)blockIdx.x * 256 + threadIdx.x;   // grid sized exactly Dd*Dd/256
    int i = (int)(idx / Dd);
    int j = (int)(idx % Dd);
    G[idx] = (i == j) ? 0.f : 0.5f * (Graw[idx] + Graw[(long)j * Dd + i]);
}

__global__ __launch_bounds__(256) void lca_init_k(const float* __restrict__ U,
                                                  float* __restrict__ V,
                                                  float* __restrict__ A0,
                                                  const float* __restrict__ loglam)
{
    long i = (long)blockIdx.x * 256 + threadIdx.x;     // grid sized exactly MT*Dd/256
    const float lam = expf(loglam[0]);
    float v = ETA * U[i];
    V[i] = v;
    float mag = fabsf(v) - lam;
    A0[i] = (mag > 0.f) ? copysignf(mag, v) : 0.f;
}

__global__ __launch_bounds__(256) void softmax_causal_k(float* __restrict__ S)
{
    const int row = blockIdx.x;                    // 0..MT-1
    const int b = row / Tt, q = row % Tt;
    float* s = S + (long)b * Tt * Tt + (long)q * Tt;
    const int n = q + 1;                           // causal: keys 0..q
    const float scale = 0.03125f;                  // 1/sqrt(1024)
    __shared__ float sh[256];
    const int tid = threadIdx.x;

    float mx = -1e30f;
    for (int j = tid; j < n; j += 256) mx = fmaxf(mx, s[j]);
    sh[tid] = mx; __syncthreads();
    for (int st = 128; st > 0; st >>= 1) { if (tid < st) sh[tid] = fmaxf(sh[tid], sh[tid+st]); __syncthreads(); }
    mx = sh[0]; __syncthreads();

    float sum = 0.f;
    for (int j = tid; j < n; j += 256) sum += __expf((s[j] - mx) * scale);
    sh[tid] = sum; __syncthreads();
    for (int st = 128; st > 0; st >>= 1) { if (tid < st) sh[tid] += sh[tid+st]; __syncthreads(); }
    const float inv = 1.f / sh[0];

    for (int j = tid; j < n; j += 256) s[j] = __expf((s[j] - mx) * scale) * inv;
    for (int j = n + tid; j < Tt; j += 256) s[j] = 0.f;   // zero masked region (read by attn@v)
}

// ---------------- launch ----------------
extern "C" void kernel_launch(void* const* d_in, const int* in_sizes, int n_in,
                              void* d_out, int out_size)
{
    const float* x     = (const float*)d_in[0];
    const float* W_qkv = (const float*)d_in[1];
    const float* W_out = (const float*)d_in[2];
    const float* Gq    = (const float*)d_in[3];
    const float* llq   = (const float*)d_in[4];
    const float* Gk    = (const float*)d_in[5];
    const float* llk   = (const float*)d_in[6];
    float* out = (float*)d_out;

    float *pG, *pqu, *pku, *pvv, *pvst, *paq, *pak, *pS, *pAO;
    cudaGetSymbolAddress((void**)&pG,   g_G);
    cudaGetSymbolAddress((void**)&pqu,  g_qu);
    cudaGetSymbolAddress((void**)&pku,  g_ku);
    cudaGetSymbolAddress((void**)&pvv,  g_vv);
    cudaGetSymbolAddress((void**)&pvst, g_vst);
    cudaGetSymbolAddress((void**)&paq,  g_aq);
    cudaGetSymbolAddress((void**)&pak,  g_ak);
    cudaGetSymbolAddress((void**)&pS,   g_scores);
    cudaGetSymbolAddress((void**)&pAO,  g_ao);
    float* pG0  = pG;
    float* pG1  = pG  + (long)Dd * Dd;
    float* paq0 = paq;
    float* paq1 = paq + (long)MT * Dd;
    float* pak0 = pak;
    float* pak1 = pak + (long)MT * Dd;

    // 1) symmetrize + zero-diag G matrices
    prep_G_k<<<(Dd*Dd)/256, 256>>>(Gq, pG0);
    prep_G_k<<<(Dd*Dd)/256, 256>>>(Gk, pG1);

    // 2) QKV projection: u_q / u_k / v  (C = x @ W^T)
    dim3 gMD(Dd/BN, MT/BM, 1);
    gemm_k<true,false><<<gMD, 256>>>(x, W_qkv,                 pqu, MT, Dd, Dd, 0,0,0, 0, nullptr,nullptr,nullptr,nullptr);
    gemm_k<true,false><<<gMD, 256>>>(x, W_qkv + (long)Dd*Dd,   pku, MT, Dd, Dd, 0,0,0, 0, nullptr,nullptr,nullptr,nullptr);
    gemm_k<true,false><<<gMD, 256>>>(x, W_qkv + 2L*Dd*Dd,      pvv, MT, Dd, Dd, 0,0,0, 0, nullptr,nullptr,nullptr,nullptr);

    // 3) LCA for q (iter 0 analytic: a=0 -> t=0; then 9 fused GEMM+update iters)
    lca_init_k<<<((long)MT*Dd)/256, 256>>>(pqu, pvst, paq0, llq);
    float* cur = paq0; float* nxt = paq1;
    for (int it = 1; it < 10; it++) {
        gemm_k<false,true><<<gMD, 256>>>(cur, pG0, nullptr, MT, Dd, Dd, 0,0,0, 0, pqu, pvst, nxt, llq);
        float* tmp = cur; cur = nxt; nxt = tmp;
    }
    float* qfin = cur;

    // 4) LCA for k
    lca_init_k<<<((long)MT*Dd)/256, 256>>>(pku, pvst, pak0, llk);
    cur = pak0; nxt = pak1;
    for (int it = 1; it < 10; it++) {
        gemm_k<false,true><<<gMD, 256>>>(cur, pG1, nullptr, MT, Dd, Dd, 0,0,0, 0, pku, pvst, nxt, llk);
        float* tmp = cur; cur = nxt; nxt = tmp;
    }
    float* kfin = cur;

    // 5) scores = q @ k^T (batched, skip fully-masked blocks)
    dim3 gTT(Tt/BN, Tt/BM, Bb);
    gemm_k<true,false><<<gTT, 256>>>(qfin, kfin, pS, Tt, Tt, Dd,
                                     (long)Tt*Dd, (long)Tt*Dd, (long)Tt*Tt, 1,
                                     nullptr,nullptr,nullptr,nullptr);

    // 6) causal softmax (scale 1/32 folded in), in-place, zeros the masked tail
    softmax_causal_k<<<MT, 256>>>(pS);

    // 7) attn @ v (batched, K-loop limited to diagonal block)
    dim3 gTD(Dd/BN, Tt/BM, Bb);
    gemm_k<false,false><<<gTD, 256>>>(pS, pvv, pAO, Tt, Dd, Tt,
                                      (long)Tt*Tt, (long)Tt*Dd, (long)Tt*Dd, 2,
                                      nullptr,nullptr,nullptr,nullptr);

    // 8) output projection: out = attn_out @ W_out^T
    gemm_k<true,false><<<gMD, 256>>>(pAO, W_out, out, MT, Dd, Dd, 0,0,0, 0,
                                     nullptr,nullptr,nullptr,nullptr);
}

// round 5
// speedup vs baseline: 2.4505x; 2.4505x over previous
#include <cuda_runtime.h>
#include <cuda_bf16.h>
#include <cstdint>
#include <math.h>

// Problem constants
#define Bb 4
#define Tt 2048
#define Dd 1024
#define MT (Bb*Tt)          // 8192
#define ETA 0.1f

// ===================== scratch (static device globals) =====================
__device__ float g_G[2][(long)Dd*Dd];
__device__ float g_qu[(long)MT*Dd];
__device__ float g_ku[(long)MT*Dd];
__device__ float g_vv[(long)MT*Dd];
__device__ float g_vt[(long)MT*Dd];          // V transposed per batch: [B][D][T]
__device__ float g_vst[(long)MT*Dd];
__device__ float g_aq[2][(long)MT*Dd];
__device__ float g_ak[2][(long)MT*Dd];
__device__ float g_scores[(long)Bb*Tt*Tt];
__device__ float g_ao[(long)MT*Dd];

// ===================== helpers =====================
__device__ __forceinline__ uint32_t smem_u32(const void* p) {
    uint32_t a;
    asm("{ .reg .u64 t; cvta.to.shared.u64 t, %1; cvt.u32.u64 %0, t; }" : "=r"(a) : "l"(p));
    return a;
}

#define LDM4(r, addr) \
    asm volatile("ldmatrix.sync.aligned.m8n8.x4.shared.b16 {%0,%1,%2,%3}, [%4];" \
        : "=r"((r)[0]), "=r"((r)[1]), "=r"((r)[2]), "=r"((r)[3]) : "r"(addr))

#define MMA(d, a, b) \
    asm volatile("mma.sync.aligned.m16n8k16.row.col.f32.bf16.bf16.f32 " \
        "{%0,%1,%2,%3}, {%4,%5,%6,%7}, {%8,%9}, {%0,%1,%2,%3};" \
        : "+f"((d)[0]), "+f"((d)[1]), "+f"((d)[2]), "+f"((d)[3]) \
        : "r"((a)[0]), "r"((a)[1]), "r"((a)[2]), "r"((a)[3]), "r"((b)[0]), "r"((b)[1]))

// fp32x4 -> bf16 hi (4) + bf16 lo (4), packed as uint2 each
__device__ __forceinline__ void split4(float4 v, uint2& hi, uint2& lo) {
    __nv_bfloat162 h01 = __float22bfloat162_rn(make_float2(v.x, v.y));
    __nv_bfloat162 h23 = __float22bfloat162_rn(make_float2(v.z, v.w));
    float2 f01 = __bfloat1622float2(h01);
    float2 f23 = __bfloat1622float2(h23);
    __nv_bfloat162 l01 = __float22bfloat162_rn(make_float2(v.x - f01.x, v.y - f01.y));
    __nv_bfloat162 l23 = __float22bfloat162_rn(make_float2(v.z - f23.x, v.w - f23.y));
    hi.x = *(uint32_t*)&h01; hi.y = *(uint32_t*)&h23;
    lo.x = *(uint32_t*)&l01; lo.y = *(uint32_t*)&l23;
}

// ===================== bf16x3 tensor GEMM =====================
// C[M,N] = A[M,K] @ B[N,K]^T, A and B K-major fp32 (ld = K).
// MODE 0: plain store.  MODE 1: LCA epilogue.  MODE 2: causal scores (skip
// blocks fully above diagonal).  MODE 3: attn@v (K-loop limited to m0+128).
#define ROWB 80u            // padded SMEM row stride in bytes (32 bf16 = 64B + 16 pad)
#define HALF 10240u         // 128 rows * 80B (one matrix half: hi or lo)
#define ASIZE 20480u        // Ah + Al
#define STG  40960u         // A halves + B halves per stage
#define SMEMSZ (2u*STG)     // 81920 bytes

template<int MODE>
__global__ __launch_bounds__(256) void bgemm(
    const float* __restrict__ A, const float* __restrict__ B, float* __restrict__ C,
    int N, int K, long sA, long sB, long sC,
    const float* __restrict__ U, float* __restrict__ V, float* __restrict__ Ao,
    const float* __restrict__ loglam)
{
    const int m0 = blockIdx.y * 128;
    const int n0 = blockIdx.x * 128;
    if (MODE == 2 && n0 >= m0 + 128) return;
    const int z = blockIdx.z;
    A += (long)z * sA; B += (long)z * sB;
    const int Kend = (MODE == 3) ? min(K, m0 + 128) : K;
    const int NC = Kend >> 5;

    extern __shared__ char smem[];
    const uint32_t smemu = smem_u32(smem);

    const int tid = threadIdx.x;
    const int wid = tid >> 5, lane = tid & 31;
    const int warpM = wid & 3, warpN = wid >> 2;
    const int sub = lane >> 3, rr = lane & 7;

    // per-lane ldmatrix row offsets (conflict-free via 80B pad)
    const uint32_t aRowOff = (uint32_t)(warpM*32 + (sub&1)*8 + rr) * ROWB + (uint32_t)(sub>>1)*16;
    const uint32_t bRowOff = (uint32_t)(warpN*64 + (sub>>1)*8 + rr) * ROWB + (uint32_t)(sub&1)*16;

    float acc[2][8][4];
    #pragma unroll
    for (int mf = 0; mf < 2; mf++)
        #pragma unroll
        for (int nf = 0; nf < 8; nf++)
            #pragma unroll
            for (int e = 0; e < 4; e++) acc[mf][nf][e] = 0.f;

    // global-load lane mapping: 4 float4 per thread per matrix per chunk
    const int grow = tid >> 3;          // +i*32
    const int gkq  = tid & 7;           // float4 index within 32-float row chunk

    float4 ra[4], rb[4];
    #pragma unroll
    for (int i = 0; i < 4; i++) {
        ra[i] = *(const float4*)(A + (long)(m0 + grow + i*32) * K + gkq*4);
        rb[i] = *(const float4*)(B + (long)(n0 + grow + i*32) * K + gkq*4);
    }
    {   // store chunk 0 -> stage 0
        char* stA = smem;
        char* stB = smem + ASIZE;
        #pragma unroll
        for (int i = 0; i < 4; i++) {
            uint2 hi, lo;
            uint32_t off = (uint32_t)(grow + i*32) * ROWB + (uint32_t)gkq*8;
            split4(ra[i], hi, lo);
            *(uint2*)(stA + off) = hi; *(uint2*)(stA + HALF + off) = lo;
            split4(rb[i], hi, lo);
            *(uint2*)(stB + off) = hi; *(uint2*)(stB + HALF + off) = lo;
        }
    }

    for (int c = 0; c < NC; c++) {
        __syncthreads();
        const int s = c & 1;
        const bool more = (c + 1 < NC);
        if (more) {
            const int k0 = (c + 1) * 32;
            #pragma unroll
            for (int i = 0; i < 4; i++) {
                ra[i] = *(const float4*)(A + (long)(m0 + grow + i*32) * K + k0 + gkq*4);
                rb[i] = *(const float4*)(B + (long)(n0 + grow + i*32) * K + k0 + gkq*4);
            }
        }

        // ---- compute chunk c from stage s ----
        const uint32_t sAh = smemu + (uint32_t)s * STG;
        const uint32_t sBh = sAh + ASIZE;
        #pragma unroll
        for (int ks = 0; ks < 2; ks++) {
            uint32_t Ah[2][4], Al[2][4], Bh[4][4], Bl[4][4];
            #pragma unroll
            for (int mf = 0; mf < 2; mf++) {
                uint32_t ad = sAh + aRowOff + (uint32_t)mf*(16*ROWB) + (uint32_t)ks*32;
                LDM4(Ah[mf], ad);
                LDM4(Al[mf], ad + HALF);
            }
            #pragma unroll
            for (int jp = 0; jp < 4; jp++) {
                uint32_t bd = sBh + bRowOff + (uint32_t)jp*(16*ROWB) + (uint32_t)ks*32;
                LDM4(Bh[jp], bd);
                LDM4(Bl[jp], bd + HALF);
            }
            #pragma unroll
            for (int mf = 0; mf < 2; mf++)
                #pragma unroll
                for (int jp = 0; jp < 4; jp++) {
                    MMA(acc[mf][2*jp],   Ah[mf], &Bh[jp][0]);
                    MMA(acc[mf][2*jp+1], Ah[mf], &Bh[jp][2]);
                    MMA(acc[mf][2*jp],   Al[mf], &Bh[jp][0]);
                    MMA(acc[mf][2*jp+1], Al[mf], &Bh[jp][2]);
                    MMA(acc[mf][2*jp],   Ah[mf], &Bl[jp][0]);
                    MMA(acc[mf][2*jp+1], Ah[mf], &Bl[jp][2]);
                }
        }

        if (more) {   // store chunk c+1 -> stage s^1
            char* stA = smem + (size_t)(s ^ 1) * STG;
            char* stB = stA + ASIZE;
            #pragma unroll
            for (int i = 0; i < 4; i++) {
                uint2 hi, lo;
                uint32_t off = (uint32_t)(grow + i*32) * ROWB + (uint32_t)gkq*8;
                split4(ra[i], hi, lo);
                *(uint2*)(stA + off) = hi; *(uint2*)(stA + HALF + off) = lo;
                split4(rb[i], hi, lo);
                *(uint2*)(stB + off) = hi; *(uint2*)(stB + HALF + off) = lo;
            }
        }
    }

    // ---- epilogue ----
    const float lam = (MODE == 1) ? expf(loglam[0]) : 0.f;
    float* Cz = (MODE == 1) ? nullptr : (C + (long)z * sC);
    #pragma unroll
    for (int mf = 0; mf < 2; mf++) {
        #pragma unroll
        for (int nf = 0; nf < 8; nf++) {
            const int rA  = m0 + warpM*32 + mf*16 + (lane >> 2);
            const int col = n0 + warpN*64 + nf*8 + (lane & 3)*2;
            const float* d = acc[mf][nf];
            #pragma unroll
            for (int h = 0; h < 2; h++) {
                long off = (long)(rA + h*8) * N + col;
                float t0 = d[2*h], t1 = d[2*h + 1];
                if (MODE == 1) {
                    float2 u2 = *(const float2*)(U + off);
                    float2 v2 = *(const float2*)(V + off);
                    float vn0 = v2.x + ETA * (u2.x - v2.x - t0);
                    float vn1 = v2.y + ETA * (u2.y - v2.y - t1);
                    *(float2*)(V + off) = make_float2(vn0, vn1);
                    float m0f = fabsf(vn0) - lam, m1f = fabsf(vn1) - lam;
                    float a0 = (m0f > 0.f) ? copysignf(m0f, vn0) : 0.f;
                    float a1 = (m1f > 0.f) ? copysignf(m1f, vn1) : 0.f;
                    *(float2*)(Ao + off) = make_float2(a0, a1);
                } else {
                    *(float2*)(Cz + off) = make_float2(t0, t1);
                }
            }
        }
    }
}

// ===================== elementwise / auxiliary kernels =====================
__global__ __launch_bounds__(256) void prep_G_k(const float* __restrict__ Graw,
                                                float* __restrict__ G)
{
    long idx = (long)blockIdx.x * 256 + threadIdx.x;
    int i = (int)(idx / Dd);
    int j = (int)(idx % Dd);
    G[idx] = (i == j) ? 0.f : 0.5f * (Graw[idx] + Graw[(long)j * Dd + i]);
}

__global__ __launch_bounds__(256) void lca_init_k(const float* __restrict__ U,
                                                  float* __restrict__ V,
                                                  float* __restrict__ A0,
                                                  const float* __restrict__ loglam)
{
    long i = (long)blockIdx.x * 256 + threadIdx.x;
    const float lam = expf(loglam[0]);
    float v = ETA * U[i];
    V[i] = v;
    float mag = fabsf(v) - lam;
    A0[i] = (mag > 0.f) ? copysignf(mag, v) : 0.f;
}

__global__ __launch_bounds__(256) void transpose_k(const float* __restrict__ in,
                                                   float* __restrict__ outp)
{
    __shared__ float tile[32][33];
    const int b = blockIdx.z;
    const int t0 = blockIdx.x * 32, d0 = blockIdx.y * 32;
    in   += (long)b * Tt * Dd;
    outp += (long)b * Tt * Dd;
    const int tx = threadIdx.x, ty = threadIdx.y;   // 32 x 8
    #pragma unroll
    for (int i = 0; i < 32; i += 8)
        tile[ty + i][tx] = in[(long)(t0 + ty + i) * Dd + d0 + tx];
    __syncthreads();
    #pragma unroll
    for (int i = 0; i < 32; i += 8)
        outp[(long)(d0 + ty + i) * Tt + t0 + tx] = tile[tx][ty + i];
}

__global__ __launch_bounds__(256) void softmax_causal_k(float* __restrict__ S)
{
    const int row = blockIdx.x;
    const int b = row / Tt, q = row % Tt;
    float* s = S + (long)b * Tt * Tt + (long)q * Tt;
    const int n = q + 1;
    const float scale = 0.03125f;                  // 1/sqrt(1024)
    __shared__ float sh[256];
    const int tid = threadIdx.x;

    float mx = -1e30f;
    for (int j = tid; j < n; j += 256) mx = fmaxf(mx, s[j]);
    sh[tid] = mx; __syncthreads();
    for (int st = 128; st > 0; st >>= 1) { if (tid < st) sh[tid] = fmaxf(sh[tid], sh[tid+st]); __syncthreads(); }
    mx = sh[0]; __syncthreads();

    float sum = 0.f;
    for (int j = tid; j < n; j += 256) sum += __expf((s[j] - mx) * scale);
    sh[tid] = sum; __syncthreads();
    for (int st = 128; st > 0; st >>= 1) { if (tid < st) sh[tid] += sh[tid+st]; __syncthreads(); }
    const float inv = 1.f / sh[0];

    for (int j = tid; j < n; j += 256) s[j] = __expf((s[j] - mx) * scale) * inv;
    for (int j = n + tid; j < Tt; j += 256) s[j] = 0.f;
}

// ===================== launch =====================
extern "C" void kernel_launch(void* const* d_in, const int* in_sizes, int n_in,
                              void* d_out, int out_size)
{
    const float* x     = (const float*)d_in[0];
    const float* W_qkv = (const float*)d_in[1];
    const float* W_out = (const float*)d_in[2];
    const float* Gq    = (const float*)d_in[3];
    const float* llq   = (const float*)d_in[4];
    const float* Gk    = (const float*)d_in[5];
    const float* llk   = (const float*)d_in[6];
    float* out = (float*)d_out;

    cudaFuncSetAttribute(bgemm<0>, cudaFuncAttributeMaxDynamicSharedMemorySize, SMEMSZ);
    cudaFuncSetAttribute(bgemm<1>, cudaFuncAttributeMaxDynamicSharedMemorySize, SMEMSZ);
    cudaFuncSetAttribute(bgemm<2>, cudaFuncAttributeMaxDynamicSharedMemorySize, SMEMSZ);
    cudaFuncSetAttribute(bgemm<3>, cudaFuncAttributeMaxDynamicSharedMemorySize, SMEMSZ);

    float *pG, *pqu, *pku, *pvv, *pvt, *pvst, *paq, *pak, *pS, *pAO;
    cudaGetSymbolAddress((void**)&pG,   g_G);
    cudaGetSymbolAddress((void**)&pqu,  g_qu);
    cudaGetSymbolAddress((void**)&pku,  g_ku);
    cudaGetSymbolAddress((void**)&pvv,  g_vv);
    cudaGetSymbolAddress((void**)&pvt,  g_vt);
    cudaGetSymbolAddress((void**)&pvst, g_vst);
    cudaGetSymbolAddress((void**)&paq,  g_aq);
    cudaGetSymbolAddress((void**)&pak,  g_ak);
    cudaGetSymbolAddress((void**)&pS,   g_scores);
    cudaGetSymbolAddress((void**)&pAO,  g_ao);
    float* pG0  = pG;
    float* pG1  = pG  + (long)Dd * Dd;
    float* paq0 = paq;
    float* paq1 = paq + (long)MT * Dd;
    float* pak0 = pak;
    float* pak1 = pak + (long)MT * Dd;

    // 1) symmetrize + zero-diag G
    prep_G_k<<<(Dd*Dd)/256, 256>>>(Gq, pG0);
    prep_G_k<<<(Dd*Dd)/256, 256>>>(Gk, pG1);

    // 2) QKV projection: C = x @ W^T (W rows K-major)
    dim3 gMD(Dd/128, MT/128, 1);   // (8, 64)
    bgemm<0><<<gMD, 256, SMEMSZ>>>(x, W_qkv,               pqu, Dd, Dd, 0,0,0, nullptr,nullptr,nullptr,nullptr);
    bgemm<0><<<gMD, 256, SMEMSZ>>>(x, W_qkv + (long)Dd*Dd, pku, Dd, Dd, 0,0,0, nullptr,nullptr,nullptr,nullptr);
    bgemm<0><<<gMD, 256, SMEMSZ>>>(x, W_qkv + 2L*Dd*Dd,    pvv, Dd, Dd, 0,0,0, nullptr,nullptr,nullptr,nullptr);

    // 3) LCA for q (G symmetric zero-diag: a@G == a@G^T, row-major G is K-major B)
    lca_init_k<<<((long)MT*Dd)/256, 256>>>(pqu, pvst, paq0, llq);
    float* cur = paq0; float* nxt = paq1;
    for (int it = 1; it < 10; it++) {
        bgemm<1><<<gMD, 256, SMEMSZ>>>(cur, pG0, nullptr, Dd, Dd, 0,0,0, pqu, pvst, nxt, llq);
        float* tmp = cur; cur = nxt; nxt = tmp;
    }
    float* qfin = cur;

    // 4) LCA for k
    lca_init_k<<<((long)MT*Dd)/256, 256>>>(pku, pvst, pak0, llk);
    cur = pak0; nxt = pak1;
    for (int it = 1; it < 10; it++) {
        bgemm<1><<<gMD, 256, SMEMSZ>>>(cur, pG1, nullptr, Dd, Dd, 0,0,0, pku, pvst, nxt, llk);
        float* tmp = cur; cur = nxt; nxt = tmp;
    }
    float* kfin = cur;

    // 5) scores = q @ k^T (batched, skip fully-masked blocks)
    dim3 gTT(Tt/128, Tt/128, Bb);  // (16, 16, 4)
    bgemm<2><<<gTT, 256, SMEMSZ>>>(qfin, kfin, pS, Tt, Dd,
                                   (long)Tt*Dd, (long)Tt*Dd, (long)Tt*Tt,
                                   nullptr,nullptr,nullptr,nullptr);

    // 6) causal softmax (in-place, zeroes masked tail)
    softmax_causal_k<<<MT, 256>>>(pS);

    // 7) transpose V per batch -> Vt [B][D][T] (K-major for attn@v)
    transpose_k<<<dim3(Tt/32, Dd/32, Bb), dim3(32, 8)>>>(pvv, pvt);

    // 8) attn @ v = P @ Vt^T (K = T, limited to diagonal block)
    dim3 gTD(Dd/128, Tt/128, Bb);  // (8, 16, 4)
    bgemm<3><<<gTD, 256, SMEMSZ>>>(pS, pvt, pAO, Dd, Tt,
                                   (long)Tt*Tt, (long)Tt*Dd, (long)Tt*Dd,
                                   nullptr,nullptr,nullptr,nullptr);

    // 9) output projection
    bgemm<0><<<gMD, 256, SMEMSZ>>>(pAO, W_out, out, Dd, Dd, 0,0,0,
                                   nullptr,nullptr,nullptr,nullptr);
}

// round 6
// speedup vs baseline: 2.4509x; 1.0001x over previous
#include <cuda_runtime.h>
#include <cuda_bf16.h>
#include <cstdint>
#include <math.h>

// Problem constants
#define Bb 4
#define Tt 2048
#define Dd 1024
#define MT (Bb*Tt)          // 8192
#define ETA 0.1f

// ===================== scratch (static device globals) =====================
// bf16 hi/lo operand planes
__device__ __nv_bfloat16 g_xh[(long)MT*Dd],  g_xl[(long)MT*Dd];
__device__ __nv_bfloat16 g_Wqh[3L*Dd*Dd],    g_Wql[3L*Dd*Dd];
__device__ __nv_bfloat16 g_Woh[(long)Dd*Dd], g_Wol[(long)Dd*Dd];
__device__ __nv_bfloat16 g_Gh[2][(long)Dd*Dd], g_Gl[2][(long)Dd*Dd];
__device__ __nv_bfloat16 g_aqh[2][(long)MT*Dd], g_aql[2][(long)MT*Dd];
__device__ __nv_bfloat16 g_akh[2][(long)MT*Dd], g_akl[2][(long)MT*Dd];
__device__ __nv_bfloat16 g_Ph[(long)Bb*Tt*Tt],  g_Pl[(long)Bb*Tt*Tt];
__device__ __nv_bfloat16 g_Vth[(long)MT*Dd], g_Vtl[(long)MT*Dd];
__device__ __nv_bfloat16 g_AOh[(long)MT*Dd], g_AOl[(long)MT*Dd];
// fp32 state
__device__ float g_qu[(long)MT*Dd];
__device__ float g_ku[(long)MT*Dd];
__device__ float g_vstq[(long)MT*Dd];
__device__ float g_vstk[(long)MT*Dd];
__device__ float g_vv[(long)MT*Dd];
__device__ float g_scores[(long)Bb*Tt*Tt];

// ===================== helpers =====================
__device__ __forceinline__ uint32_t smem_u32(const void* p) {
    uint32_t a;
    asm("{ .reg .u64 t; cvta.to.shared.u64 t, %1; cvt.u32.u64 %0, t; }" : "=r"(a) : "l"(p));
    return a;
}
#define LDM4(r, addr) \
    asm volatile("ldmatrix.sync.aligned.m8n8.x4.shared.b16 {%0,%1,%2,%3}, [%4];" \
        : "=r"((r)[0]), "=r"((r)[1]), "=r"((r)[2]), "=r"((r)[3]) : "r"(addr))
#define MMA(d, a, b) \
    asm volatile("mma.sync.aligned.m16n8k16.row.col.f32.bf16.bf16.f32 " \
        "{%0,%1,%2,%3}, {%4,%5,%6,%7}, {%8,%9}, {%0,%1,%2,%3};" \
        : "+f"((d)[0]), "+f"((d)[1]), "+f"((d)[2]), "+f"((d)[3]) \
        : "r"((a)[0]), "r"((a)[1]), "r"((a)[2]), "r"((a)[3]), "r"((b)[0]), "r"((b)[1]))
#define CP16(dst, src) \
    asm volatile("cp.async.cg.shared.global [%0], [%1], 16;" :: "r"(dst), "l"(src))
#define CP_COMMIT() asm volatile("cp.async.commit_group;" ::: "memory")
#define CP_WAIT(n)  asm volatile("cp.async.wait_group %0;" :: "n"(n) : "memory")

// write a fp32 pair (a0,a1) as bf16 hi/lo planes
__device__ __forceinline__ void wpair(__nv_bfloat16* __restrict__ H,
                                      __nv_bfloat16* __restrict__ L,
                                      long off, float a0, float a1) {
    __nv_bfloat162 h = __float22bfloat162_rn(make_float2(a0, a1));
    float2 hf = __bfloat1622float2(h);
    __nv_bfloat162 l = __float22bfloat162_rn(make_float2(a0 - hf.x, a1 - hf.y));
    *(__nv_bfloat162*)(H + off) = h;
    *(__nv_bfloat162*)(L + off) = l;
}

// smem swizzled address: 64B rows, 16B chunk c xored with (row>>1)&3
__device__ __forceinline__ uint32_t swadr(uint32_t base, int r, int c) {
    return base + (uint32_t)r * 64u + (uint32_t)((c ^ ((r >> 1) & 3)) << 4);
}

// ===================== bf16x3 tensor GEMM, cp.async 4-stage pipeline =====================
// C[M,N] = A[M,K] @ B[N,K]^T from pre-split bf16 hi/lo planes (ld = K).
// MODE 0: fp32 store.           MODE 1: LCA epilogue (U,V fp32; a -> bf16 pair).
// MODE 2: causal scores fp32.   MODE 3: attn@v, K limited, out -> bf16 pair.
// MODE 4: QKV q/k: U=t, V=ETA*t, a0=soft(ETA*t) -> bf16 pair.
#define NSTG 4
#define STGB 32768u          // Ah 8K | Al 8K | Bh 8K | Bl 8K
#define SMEMSZ (NSTG*STGB)   // 131072

template<int MODE>
__global__ __launch_bounds__(256) void bgemm(
    const __nv_bfloat16* __restrict__ Ah, const __nv_bfloat16* __restrict__ Al,
    const __nv_bfloat16* __restrict__ Bh, const __nv_bfloat16* __restrict__ Bl,
    float* __restrict__ C, int N, int K, long sA, long sB, long sC,
    const float* __restrict__ U, float* __restrict__ V,
    __nv_bfloat16* __restrict__ Aoh, __nv_bfloat16* __restrict__ Aol,
    const float* __restrict__ loglam)
{
    const int m0 = blockIdx.y * 128;
    const int n0 = blockIdx.x * 128;
    if (MODE == 2 && n0 >= m0 + 128) return;
    const int z = blockIdx.z;
    Ah += (long)z * sA; Al += (long)z * sA;
    Bh += (long)z * sB; Bl += (long)z * sB;
    if (MODE == 3) { Aoh += (long)z * sC; Aol += (long)z * sC; }

    const int Kend = (MODE == 3) ? min(K, m0 + 128) : K;
    const int NC = Kend >> 5;

    extern __shared__ char smem[];
    const uint32_t smemu = smem_u32(smem);
    const int tid  = threadIdx.x;
    const int wid  = tid >> 5, lane = tid & 31;
    const int warpM = wid & 3, warpN = wid >> 2;
    const int sub = lane >> 3, rr = lane & 7;

    float acc[2][8][4];
    #pragma unroll
    for (int mf = 0; mf < 2; mf++)
        #pragma unroll
        for (int nf = 0; nf < 8; nf++)
            #pragma unroll
            for (int e = 0; e < 4; e++) acc[mf][nf][e] = 0.f;

    // cp.async lane mapping: 2048 x 16B chunks/stage, 8 per thread
    // id -> half h (Ah,Al,Bh,Bl), row (0..127), chunk c (0..3)
    auto issue = [&](int st, int kc) {
        const uint32_t sbase = smemu + (uint32_t)st * STGB;
        const int k0 = kc * 32;
        #pragma unroll
        for (int i = 0; i < 8; i++) {
            const int id = tid + i * 256;
            const int h = id >> 9, rem = id & 511;
            const int row = rem >> 2, cc = rem & 3;
            const __nv_bfloat16* src;
            if (h == 0)      src = Ah + (long)(m0 + row) * K + k0 + cc * 8;
            else if (h == 1) src = Al + (long)(m0 + row) * K + k0 + cc * 8;
            else if (h == 2) src = Bh + (long)(n0 + row) * K + k0 + cc * 8;
            else             src = Bl + (long)(n0 + row) * K + k0 + cc * 8;
            const uint32_t dst = swadr(sbase + (uint32_t)h * 8192u, row, cc);
            CP16(dst, src);
        }
    };

    // prologue: stages 0..NSTG-2
    #pragma unroll
    for (int s = 0; s < NSTG - 1; s++) {
        if (s < NC) issue(s, s);
        CP_COMMIT();
    }

    for (int c = 0; c < NC; c++) {
        CP_WAIT(NSTG - 2);
        __syncthreads();
        const int pf = c + NSTG - 1;
        if (pf < NC) issue(pf & (NSTG - 1), pf);
        CP_COMMIT();

        // ---- compute chunk c ----
        const uint32_t sb0 = smemu + (uint32_t)(c & (NSTG - 1)) * STGB;
        #pragma unroll
        for (int ks = 0; ks < 2; ks++) {
            uint32_t Ahf[2][4], Alf[2][4], Bhf[4][4], Blf[4][4];
            #pragma unroll
            for (int mf = 0; mf < 2; mf++) {
                const int r = warpM * 32 + mf * 16 + (sub & 1) * 8 + rr;
                const uint32_t ad = swadr(sb0, r, ks * 2 + (sub >> 1));
                LDM4(Ahf[mf], ad);
                LDM4(Alf[mf], ad + 8192u);
            }
            #pragma unroll
            for (int jp = 0; jp < 4; jp++) {
                const int r = warpN * 64 + jp * 16 + (sub >> 1) * 8 + rr;
                const uint32_t bd = swadr(sb0 + 16384u, r, ks * 2 + (sub & 1));
                LDM4(Bhf[jp], bd);
                LDM4(Blf[jp], bd + 8192u);
            }
            #pragma unroll
            for (int mf = 0; mf < 2; mf++)
                #pragma unroll
                for (int jp = 0; jp < 4; jp++) {
                    MMA(acc[mf][2*jp],   Ahf[mf], &Bhf[jp][0]);
                    MMA(acc[mf][2*jp+1], Ahf[mf], &Bhf[jp][2]);
                    MMA(acc[mf][2*jp],   Alf[mf], &Bhf[jp][0]);
                    MMA(acc[mf][2*jp+1], Alf[mf], &Bhf[jp][2]);
                    MMA(acc[mf][2*jp],   Ahf[mf], &Blf[jp][0]);
                    MMA(acc[mf][2*jp+1], Ahf[mf], &Blf[jp][2]);
                }
        }
    }

    // ---- epilogue ----
    const float lam = (MODE == 1 || MODE == 4) ? expf(loglam[0]) : 0.f;
    float* Cz = C + (long)z * sC;
    #pragma unroll
    for (int mf = 0; mf < 2; mf++) {
        #pragma unroll
        for (int nf = 0; nf < 8; nf++) {
            const int rA  = m0 + warpM*32 + mf*16 + (lane >> 2);
            const int col = n0 + warpN*64 + nf*8 + (lane & 3)*2;
            const float* d = acc[mf][nf];
            #pragma unroll
            for (int hh = 0; hh < 2; hh++) {
                const long off = (long)(rA + hh*8) * N + col;
                const float t0 = d[2*hh], t1 = d[2*hh + 1];
                if (MODE == 1) {
                    float2 u2 = *(const float2*)(U + off);
                    float2 v2 = *(const float2*)(V + off);
                    float vn0 = v2.x + ETA * (u2.x - v2.x - t0);
                    float vn1 = v2.y + ETA * (u2.y - v2.y - t1);
                    *(float2*)(V + off) = make_float2(vn0, vn1);
                    float mm0 = fabsf(vn0) - lam, mm1 = fabsf(vn1) - lam;
                    wpair(Aoh, Aol, off,
                          (mm0 > 0.f) ? copysignf(mm0, vn0) : 0.f,
                          (mm1 > 0.f) ? copysignf(mm1, vn1) : 0.f);
                } else if (MODE == 4) {
                    *(float2*)((float*)U + off) = make_float2(t0, t1);
                    float vn0 = ETA * t0, vn1 = ETA * t1;
                    *(float2*)(V + off) = make_float2(vn0, vn1);
                    float mm0 = fabsf(vn0) - lam, mm1 = fabsf(vn1) - lam;
                    wpair(Aoh, Aol, off,
                          (mm0 > 0.f) ? copysignf(mm0, vn0) : 0.f,
                          (mm1 > 0.f) ? copysignf(mm1, vn1) : 0.f);
                } else if (MODE == 3) {
                    wpair(Aoh, Aol, off, t0, t1);
                } else {
                    *(float2*)(Cz + off) = make_float2(t0, t1);
                }
            }
        }
    }
}

// ===================== elementwise / auxiliary kernels =====================
__global__ __launch_bounds__(256) void split_k(const float* __restrict__ src,
                                               __nv_bfloat16* __restrict__ h,
                                               __nv_bfloat16* __restrict__ l)
{
    long i = (long)blockIdx.x * 256 + threadIdx.x;
    float v = src[i];
    __nv_bfloat16 hb = __float2bfloat16(v);
    h[i] = hb;
    l[i] = __float2bfloat16(v - __bfloat162float(hb));
}

__global__ __launch_bounds__(256) void prepG_split_k(const float* __restrict__ Graw,
                                                     __nv_bfloat16* __restrict__ h,
                                                     __nv_bfloat16* __restrict__ l)
{
    long idx = (long)blockIdx.x * 256 + threadIdx.x;
    int i = (int)(idx / Dd), j = (int)(idx % Dd);
    float g = (i == j) ? 0.f : 0.5f * (Graw[idx] + Graw[(long)j * Dd + i]);
    __nv_bfloat16 hb = __float2bfloat16(g);
    h[idx] = hb;
    l[idx] = __float2bfloat16(g - __bfloat162float(hb));
}

__global__ __launch_bounds__(256) void transpose_split_k(const float* __restrict__ in,
                                                         __nv_bfloat16* __restrict__ oh,
                                                         __nv_bfloat16* __restrict__ ol)
{
    __shared__ float tile[32][33];
    const int b = blockIdx.z;
    const int t0 = blockIdx.x * 32, d0 = blockIdx.y * 32;
    in += (long)b * Tt * Dd;
    oh += (long)b * Tt * Dd;
    ol += (long)b * Tt * Dd;
    const int tx = threadIdx.x, ty = threadIdx.y;   // 32 x 8
    #pragma unroll
    for (int i = 0; i < 32; i += 8)
        tile[ty + i][tx] = in[(long)(t0 + ty + i) * Dd + d0 + tx];
    __syncthreads();
    #pragma unroll
    for (int i = 0; i < 32; i += 8) {
        float v = tile[tx][ty + i];
        long off = (long)(d0 + ty + i) * Tt + t0 + tx;
        __nv_bfloat16 hb = __float2bfloat16(v);
        oh[off] = hb;
        ol[off] = __float2bfloat16(v - __bfloat162float(hb));
    }
}

__global__ __launch_bounds__(256) void softmax_causal_k(const float* __restrict__ S,
                                                        __nv_bfloat16* __restrict__ Ph,
                                                        __nv_bfloat16* __restrict__ Pl)
{
    const int row = blockIdx.x;
    const int b = row / Tt, q = row % Tt;
    const long base = (long)b * Tt * Tt + (long)q * Tt;
    const float* s = S + base;
    const int n = q + 1;
    const float scale = 0.03125f;                  // 1/sqrt(1024)
    __shared__ float sh[256];
    const int tid = threadIdx.x;

    float mx = -1e30f;
    for (int j = tid; j < n; j += 256) mx = fmaxf(mx, s[j]);
    sh[tid] = mx; __syncthreads();
    for (int st = 128; st > 0; st >>= 1) { if (tid < st) sh[tid] = fmaxf(sh[tid], sh[tid+st]); __syncthreads(); }
    mx = sh[0]; __syncthreads();

    float sum = 0.f;
    for (int j = tid; j < n; j += 256) sum += __expf((s[j] - mx) * scale);
    sh[tid] = sum; __syncthreads();
    for (int st = 128; st > 0; st >>= 1) { if (tid < st) sh[tid] += sh[tid+st]; __syncthreads(); }
    const float inv = 1.f / sh[0];

    for (int j = tid; j < n; j += 256) {
        float p = __expf((s[j] - mx) * scale) * inv;
        __nv_bfloat16 hb = __float2bfloat16(p);
        Ph[base + j] = hb;
        Pl[base + j] = __float2bfloat16(p - __bfloat162float(hb));
    }
    const __nv_bfloat16 zz = __float2bfloat16(0.f);
    for (int j = n + tid; j < Tt; j += 256) { Ph[base + j] = zz; Pl[base + j] = zz; }
}

// ===================== launch =====================
extern "C" void kernel_launch(void* const* d_in, const int* in_sizes, int n_in,
                              void* d_out, int out_size)
{
    const float* x     = (const float*)d_in[0];
    const float* W_qkv = (const float*)d_in[1];
    const float* W_out = (const float*)d_in[2];
    const float* Gq    = (const float*)d_in[3];
    const float* llq   = (const float*)d_in[4];
    const float* Gk    = (const float*)d_in[5];
    const float* llk   = (const float*)d_in[6];
    float* out = (float*)d_out;

    cudaFuncSetAttribute(bgemm<0>, cudaFuncAttributeMaxDynamicSharedMemorySize, SMEMSZ);
    cudaFuncSetAttribute(bgemm<1>, cudaFuncAttributeMaxDynamicSharedMemorySize, SMEMSZ);
    cudaFuncSetAttribute(bgemm<2>, cudaFuncAttributeMaxDynamicSharedMemorySize, SMEMSZ);
    cudaFuncSetAttribute(bgemm<3>, cudaFuncAttributeMaxDynamicSharedMemorySize, SMEMSZ);
    cudaFuncSetAttribute(bgemm<4>, cudaFuncAttributeMaxDynamicSharedMemorySize, SMEMSZ);

    __nv_bfloat16 *pxh, *pxl, *pWqh, *pWql, *pWoh, *pWol, *pGh, *pGl;
    __nv_bfloat16 *paqh, *paql, *pakh, *pakl, *pPh, *pPl, *pVth, *pVtl, *pAOh, *pAOl;
    float *pqu, *pku, *pvstq, *pvstk, *pvv, *pS;
    cudaGetSymbolAddress((void**)&pxh, g_xh);   cudaGetSymbolAddress((void**)&pxl, g_xl);
    cudaGetSymbolAddress((void**)&pWqh, g_Wqh); cudaGetSymbolAddress((void**)&pWql, g_Wql);
    cudaGetSymbolAddress((void**)&pWoh, g_Woh); cudaGetSymbolAddress((void**)&pWol, g_Wol);
    cudaGetSymbolAddress((void**)&pGh, g_Gh);   cudaGetSymbolAddress((void**)&pGl, g_Gl);
    cudaGetSymbolAddress((void**)&paqh, g_aqh); cudaGetSymbolAddress((void**)&paql, g_aql);
    cudaGetSymbolAddress((void**)&pakh, g_akh); cudaGetSymbolAddress((void**)&pakl, g_akl);
    cudaGetSymbolAddress((void**)&pPh, g_Ph);   cudaGetSymbolAddress((void**)&pPl, g_Pl);
    cudaGetSymbolAddress((void**)&pVth, g_Vth); cudaGetSymbolAddress((void**)&pVtl, g_Vtl);
    cudaGetSymbolAddress((void**)&pAOh, g_AOh); cudaGetSymbolAddress((void**)&pAOl, g_AOl);
    cudaGetSymbolAddress((void**)&pqu, g_qu);   cudaGetSymbolAddress((void**)&pku, g_ku);
    cudaGetSymbolAddress((void**)&pvstq, g_vstq); cudaGetSymbolAddress((void**)&pvstk, g_vstk);
    cudaGetSymbolAddress((void**)&pvv, g_vv);   cudaGetSymbolAddress((void**)&pS, g_scores);

    const long PD = (long)MT * Dd;       // plane size for a/AO/Vt
    const long GD = (long)Dd * Dd;

    // 1) one-time splits
    split_k<<<(int)(PD/256), 256>>>(x, pxh, pxl);
    split_k<<<(int)(3*GD/256), 256>>>(W_qkv, pWqh, pWql);
    split_k<<<(int)(GD/256), 256>>>(W_out, pWoh, pWol);
    prepG_split_k<<<(int)(GD/256), 256>>>(Gq, pGh, pGl);
    prepG_split_k<<<(int)(GD/256), 256>>>(Gk, pGh + GD, pGl + GD);

    // 2) QKV: q,k fused with LCA init (MODE 4); v plain (MODE 0)
    dim3 gMD(Dd/128, MT/128, 1);   // (8, 64)
    bgemm<4><<<gMD, 256, SMEMSZ>>>(pxh, pxl, pWqh,        pWql,        nullptr, Dd, Dd, 0,0,0,
                                   pqu, pvstq, paqh, paql, llq);
    bgemm<4><<<gMD, 256, SMEMSZ>>>(pxh, pxl, pWqh + GD,   pWql + GD,   nullptr, Dd, Dd, 0,0,0,
                                   pku, pvstk, pakh, pakl, llk);
    bgemm<0><<<gMD, 256, SMEMSZ>>>(pxh, pxl, pWqh + 2*GD, pWql + 2*GD, pvv, Dd, Dd, 0,0,0,
                                   nullptr, nullptr, nullptr, nullptr, nullptr);

    // 3) LCA for q: 9 fused GEMM+update iterations (ping-pong planes)
    int cur = 0;
    for (int it = 1; it < 10; it++) {
        int nxt = cur ^ 1;
        bgemm<1><<<gMD, 256, SMEMSZ>>>(paqh + cur*PD, paql + cur*PD, pGh, pGl,
                                       nullptr, Dd, Dd, 0,0,0,
                                       pqu, pvstq, paqh + nxt*PD, paql + nxt*PD, llq);
        cur = nxt;
    }
    const int qf = cur;

    // 4) LCA for k
    cur = 0;
    for (int it = 1; it < 10; it++) {
        int nxt = cur ^ 1;
        bgemm<1><<<gMD, 256, SMEMSZ>>>(pakh + cur*PD, pakl + cur*PD, pGh + GD, pGl + GD,
                                       nullptr, Dd, Dd, 0,0,0,
                                       pku, pvstk, pakh + nxt*PD, pakl + nxt*PD, llk);
        cur = nxt;
    }
    const int kf = cur;

    // 5) scores = q @ k^T (batched, skip fully-masked blocks)
    dim3 gTT(Tt/128, Tt/128, Bb);  // (16, 16, 4)
    bgemm<2><<<gTT, 256, SMEMSZ>>>(paqh + qf*PD, paql + qf*PD, pakh + kf*PD, pakl + kf*PD,
                                   pS, Tt, Dd, (long)Tt*Dd, (long)Tt*Dd, (long)Tt*Tt,
                                   nullptr, nullptr, nullptr, nullptr, nullptr);

    // 6) causal softmax -> P bf16 pair (zeroed masked tail)
    softmax_causal_k<<<MT, 256>>>(pS, pPh, pPl);

    // 7) transpose+split V -> Vt planes [B][D][T]
    transpose_split_k<<<dim3(Tt/32, Dd/32, Bb), dim3(32, 8)>>>(pvv, pVth, pVtl);

    // 8) attn @ v = P @ Vt^T (K limited to diagonal block) -> AO bf16 pair
    dim3 gTD(Dd/128, Tt/128, Bb);  // (8, 16, 4)
    bgemm<3><<<gTD, 256, SMEMSZ>>>(pPh, pPl, pVth, pVtl,
                                   nullptr, Dd, Tt, (long)Tt*Tt, (long)Tt*Dd, (long)Tt*Dd,
                                   nullptr, nullptr, pAOh, pAOl, nullptr);

    // 9) output projection -> fp32 out
    bgemm<0><<<gMD, 256, SMEMSZ>>>(pAOh, pAOl, pWoh, pWol, out, Dd, Dd, 0,0,0,
                                   nullptr, nullptr, nullptr, nullptr, nullptr);
}